// round 5
// baseline (speedup 1.0000x reference)
#include <cuda_runtime.h>
#include <cuda_bf16.h>
#include <math.h>

#define NN 50000
#define NE 800000
#define NG 256
#define H 64
#define BN_EPS 1e-5f

// ------------------------ device scratch (no allocs allowed) -----------------
__device__ int   g_flag;
__device__ int   g_src[NE];
__device__ int   g_dst[NE];
__device__ int   g_batch[NN];
__device__ int   g_cnt[NN];          // statically zero; re-zeroed by scan each run
__device__ int   g_rowstart[NN + 1];
__device__ int   g_cursor[NN];
__device__ float g_invcnt[NN];
__device__ int   g_csr_src[NE];
__device__ float g_y[NN * H];        // Y = A @ Wl
__device__ float g_z[NN * H];        // Z = A @ Wr + bias
__device__ float g_hA[NN * H];
__device__ float g_hB[NN * H];
__device__ float g_pacc[NG * H];     // statically zero; re-zeroed by poolnorm
__device__ float g_pcnt[NG];         // statically zero; re-zeroed by final_kernel
__device__ float g_pool[NG * H];
__device__ float g_t1[NG * 256];
__device__ float g_t2[NG * 128];
__device__ float g_t3[NG * 64];

// ------------------------ dtype probe ---------------------------------------
__global__ void detect_kernel(const long long* ei, const long long* bt) {
    __shared__ int bad;
    if (threadIdx.x == 0) bad = 0;
    __syncthreads();
    long long v = ei[threadIdx.x];
    if (v < 0 || v >= NN) bad = 1;
    long long b = bt[threadIdx.x];
    if (b < 0 || b >= NG) bad = 1;
    __syncthreads();
    if (threadIdx.x == 0) g_flag = bad ? 0 : 1;
}

// convert + histogram fused (g_cnt must be zero on entry; scan re-zeroes it)
__global__ void convert_kernel(const void* ei, const void* bt) {
    int i = blockIdx.x * blockDim.x + threadIdx.x;
    bool is64 = (g_flag != 0);
    if (i < NE) {
        int s, d;
        if (is64) {
            const long long* p = (const long long*)ei;
            s = (int)p[i]; d = (int)p[NE + i];
        } else {
            const int* p = (const int*)ei;
            s = p[i]; d = p[NE + i];
        }
        g_src[i] = s; g_dst[i] = d;
        atomicAdd(&g_cnt[d], 1);
    }
    if (i < NN) {
        if (is64) g_batch[i] = (int)((const long long*)bt)[i];
        else      g_batch[i] = ((const int*)bt)[i];
    }
}

// ------------------------ chunked shuffle scan (1 block, 1024 threads) ------
__global__ void scan_kernel() {
    const int C = (NN + 1023) / 1024;   // 49
    int tid = threadIdx.x;
    int base = tid * C;
    int s = 0;
#pragma unroll 7
    for (int j = 0; j < C; j++) {
        int idx = base + j;
        if (idx < NN) s += g_cnt[idx];
    }
    int lane = tid & 31, wid = tid >> 5;
    int v = s;
#pragma unroll
    for (int off = 1; off < 32; off <<= 1) {
        int t = __shfl_up_sync(0xffffffffu, v, off);
        if (lane >= off) v += t;
    }
    __shared__ int wsum[32];
    if (lane == 31) wsum[wid] = v;
    __syncthreads();
    if (wid == 0) {
        int w = wsum[lane];
#pragma unroll
        for (int off = 1; off < 32; off <<= 1) {
            int t = __shfl_up_sync(0xffffffffu, w, off);
            if (lane >= off) w += t;
        }
        wsum[lane] = w;
    }
    __syncthreads();
    int pref = v - s + (wid > 0 ? wsum[wid - 1] : 0);   // exclusive prefix
#pragma unroll 7
    for (int j = 0; j < C; j++) {
        int idx = base + j;
        if (idx < NN) {
            int c = g_cnt[idx];
            g_rowstart[idx] = pref;
            g_cursor[idx] = pref;
            g_invcnt[idx] = 1.0f / (float)max(c, 1);
            pref += c;
            g_cnt[idx] = 0;                     // reset for next replay
        }
    }
    if (tid == 0) g_rowstart[NN] = NE;
}

__global__ void fill_kernel() {
    int e = blockIdx.x * blockDim.x + threadIdx.x;
    if (e < NE) {
        int d = g_dst[e];
        int pos = atomicAdd(&g_cursor[d], 1);
        g_csr_src[pos] = g_src[e];
    }
}

// ------------------ fused dual GEMM: Y = A@Wl, Z = A@Wr + bias --------------
// A: [NN,K], Wl/Wr: [K,64]. 128-row x 128-col tile, 256 threads, 8x8 microtile.
// Global loads vectorized to float4.
template <int K>
__launch_bounds__(256)
__global__ void gemm_fused(const float* __restrict__ A,
                           const float* __restrict__ Wl,
                           const float* __restrict__ Wr,
                           const float* __restrict__ bias,
                           float* __restrict__ Y, float* __restrict__ Z) {
    __shared__ float As[128 * 33];
    __shared__ float Ws[32 * 128];
    int m0 = blockIdx.x * 128;
    int tid = threadIdx.x;
    int tr = tid >> 4, tc = tid & 15;

    float acc[8][8];
#pragma unroll
    for (int r = 0; r < 8; r++)
#pragma unroll
        for (int c = 0; c < 8; c++) acc[r][c] = 0.f;

    for (int k0 = 0; k0 < K; k0 += 32) {
        // As tile: 128x32 floats = 1024 float4, 4 per thread (LDG.128)
#pragma unroll
        for (int i = 0; i < 4; i++) {
            int idx4 = i * 256 + tid;
            int r = idx4 >> 3, c4 = idx4 & 7;
            int gr = m0 + r;
            float4 v = make_float4(0.f, 0.f, 0.f, 0.f);
            if (gr < NN) v = *(const float4*)&A[gr * K + k0 + c4 * 4];
            float* dp = &As[r * 33 + c4 * 4];
            dp[0] = v.x; dp[1] = v.y; dp[2] = v.z; dp[3] = v.w;
        }
        // Ws tile: 32x128 floats = 1024 float4, 4 per thread (LDG.128)
#pragma unroll
        for (int i = 0; i < 4; i++) {
            int idx4 = i * 256 + tid;
            int r = idx4 >> 5, c = (idx4 & 31) * 4;
            float4 v = (c < 64) ? *(const float4*)&Wl[(k0 + r) * 64 + c]
                                : *(const float4*)&Wr[(k0 + r) * 64 + (c - 64)];
            *(float4*)&Ws[r * 128 + c] = v;
        }
        __syncthreads();
#pragma unroll
        for (int k = 0; k < 32; k++) {
            float a[8], w[8];
#pragma unroll
            for (int r = 0; r < 8; r++) a[r] = As[(tr * 8 + r) * 33 + k];
            float4 w0 = *(const float4*)&Ws[k * 128 + tc * 8];
            float4 w1 = *(const float4*)&Ws[k * 128 + tc * 8 + 4];
            w[0] = w0.x; w[1] = w0.y; w[2] = w0.z; w[3] = w0.w;
            w[4] = w1.x; w[5] = w1.y; w[6] = w1.z; w[7] = w1.w;
#pragma unroll
            for (int r = 0; r < 8; r++)
#pragma unroll
                for (int c = 0; c < 8; c++) acc[r][c] = fmaf(a[r], w[c], acc[r][c]);
        }
        __syncthreads();
    }

    bool isZ = (tc >= 8);
    int col = (tc & 7) * 8;
    float bv[8];
#pragma unroll
    for (int c = 0; c < 8; c++) bv[c] = isZ ? bias[col + c] : 0.f;
    float* O = isZ ? Z : Y;
#pragma unroll
    for (int r = 0; r < 8; r++) {
        int gr = m0 + tr * 8 + r;
        if (gr < NN) {
            float4 v0, v1;
            v0.x = acc[r][0] + bv[0]; v0.y = acc[r][1] + bv[1];
            v0.z = acc[r][2] + bv[2]; v0.w = acc[r][3] + bv[3];
            v1.x = acc[r][4] + bv[4]; v1.y = acc[r][5] + bv[5];
            v1.z = acc[r][6] + bv[6]; v1.w = acc[r][7] + bv[7];
            *(float4*)&O[gr * 64 + col] = v0;
            *(float4*)&O[gr * 64 + col + 4] = v1;
        }
    }
}

// -------- aggregation + combine: h = ic * sum(Y[src]) + Z  (warp/node) ------
// Neighbor indices are fetched 32-at-a-time with a coalesced lane-parallel
// load and broadcast via shfl -> gather addresses are all known up front,
// so the gathers pipeline (MLP>=4) instead of a serial LDG->LDG chain.
template <bool POOL>
__global__ void aggregate_kernel(float* __restrict__ Hout) {
    int w = (blockIdx.x * blockDim.x + threadIdx.x) >> 5;
    int lane = threadIdx.x & 31;
    if (w >= NN) return;
    int s0 = g_rowstart[w], s1 = g_rowstart[w + 1];
    float ax = 0.f, ay = 0.f;
    for (int base = s0; base < s1; base += 32) {
        int rem = s1 - base;
        int idx = (lane < rem) ? g_csr_src[base + lane] : 0;
        int m = rem < 32 ? rem : 32;
#pragma unroll 4
        for (int j = 0; j < m; j++) {
            int s = __shfl_sync(0xffffffffu, idx, j);
            float2 v = *(const float2*)&g_y[s * 64 + lane * 2];
            ax += v.x; ay += v.y;
        }
    }
    float ic = g_invcnt[w];
    float2 z = *(const float2*)&g_z[w * 64 + lane * 2];
    float ox = ax * ic + z.x, oy = ay * ic + z.y;
    if (POOL) {
        int g = g_batch[w];
        atomicAdd(&g_pacc[g * 64 + lane * 2 + 0], ox);
        atomicAdd(&g_pacc[g * 64 + lane * 2 + 1], oy);
        if (lane == 0) atomicAdd(&g_pcnt[g], 1.f);
    } else {
        float2 o; o.x = ox; o.y = oy;
        *(float2*)&Hout[w * 64 + lane * 2] = o;
    }
}

// normalize pool; re-zero pacc for next replay (pcnt zeroed in final_kernel)
__global__ void poolnorm_kernel() {
    int i = blockIdx.x * blockDim.x + threadIdx.x;
    if (i < NG * H) {
        float c = g_pcnt[i >> 6];
        g_pool[i] = g_pacc[i] / fmaxf(c, 1.f);
        g_pacc[i] = 0.f;
    }
}

// ---------------- fused head layer: X = tanh(BN(A@W + b)) -------------------
// grid = N output features (one column per block), block = 256 graph rows.
template <int K, int N>
__launch_bounds__(256)
__global__ void head_kernel(const float* __restrict__ A, const float* __restrict__ W,
                            const float* __restrict__ b,
                            const float* __restrict__ gam, const float* __restrict__ bet,
                            float* __restrict__ X) {
    __shared__ float As[256 * 33];
    int j = blockIdx.x, i = threadIdx.x;
    float acc = b[j];
    for (int k0 = 0; k0 < K; k0 += 32) {
#pragma unroll
        for (int t = 0; t < 32; t++) {
            int idx = t * 256 + i;
            int r = idx >> 5, c = idx & 31;
            As[r * 33 + c] = A[r * K + k0 + c];
        }
        __syncthreads();
#pragma unroll
        for (int kk = 0; kk < 32; kk++)
            acc = fmaf(As[i * 33 + kk], W[(k0 + kk) * N + j], acc);
        __syncthreads();
    }
    __shared__ float red[256];
    red[i] = acc;
    __syncthreads();
    for (int off = 128; off > 0; off >>= 1) {
        if (i < off) red[i] += red[i + off];
        __syncthreads();
    }
    float mean = red[0] * (1.f / 256.f);
    __syncthreads();
    float d = acc - mean;
    red[i] = d * d;
    __syncthreads();
    for (int off = 128; off > 0; off >>= 1) {
        if (i < off) red[i] += red[i + off];
        __syncthreads();
    }
    float var = red[0] * (1.f / 256.f);
    X[i * N + j] = tanhf(d * rsqrtf(var + BN_EPS) * gam[j] + bet[j]);
}

// final linear (no BN); also re-zeroes g_pcnt for the next replay
__launch_bounds__(256)
__global__ void final_kernel(const float* __restrict__ A, const float* __restrict__ W,
                             const float* __restrict__ b, float* __restrict__ out) {
    __shared__ float As[256 * 33];
    int j = blockIdx.x, i = threadIdx.x;   // 10 blocks x 256 rows
    float acc = b[j];
    for (int k0 = 0; k0 < 64; k0 += 32) {
#pragma unroll
        for (int t = 0; t < 32; t++) {
            int idx = t * 256 + i;
            int r = idx >> 5, c = idx & 31;
            As[r * 33 + c] = A[r * 64 + k0 + c];
        }
        __syncthreads();
#pragma unroll
        for (int kk = 0; kk < 32; kk++)
            acc = fmaf(As[i * 33 + kk], W[(k0 + kk) * 10 + j], acc);
        __syncthreads();
    }
    out[i * 10 + j] = acc;
    if (j == 0) g_pcnt[i] = 0.f;
}

// ------------------------ launch --------------------------------------------
extern "C" void kernel_launch(void* const* d_in, const int* in_sizes, int n_in,
                              void* d_out, int out_size) {
    const float* x      = (const float*)d_in[0];
    const void*  ei     = d_in[1];
    const void*  bt     = d_in[2];
    const float* W1l    = (const float*)d_in[3];
    const float* b1l    = (const float*)d_in[4];
    const float* W1r    = (const float*)d_in[5];
    const float* W2l    = (const float*)d_in[6];
    const float* b2l    = (const float*)d_in[7];
    const float* W2r    = (const float*)d_in[8];
    const float* W3l    = (const float*)d_in[9];
    const float* b3l    = (const float*)d_in[10];
    const float* W3r    = (const float*)d_in[11];
    const float* lin1_w = (const float*)d_in[12];
    const float* lin1_b = (const float*)d_in[13];
    const float* g1     = (const float*)d_in[14];
    const float* be1    = (const float*)d_in[15];
    const float* lin2_w = (const float*)d_in[16];
    const float* lin2_b = (const float*)d_in[17];
    const float* g2     = (const float*)d_in[18];
    const float* be2    = (const float*)d_in[19];
    const float* lin3_w = (const float*)d_in[20];
    const float* lin3_b = (const float*)d_in[21];
    const float* g3     = (const float*)d_in[22];
    const float* be3    = (const float*)d_in[23];
    const float* lin4_w = (const float*)d_in[24];
    const float* lin4_b = (const float*)d_in[25];
    float* out = (float*)d_out;

    float *pY, *pZ, *pHA, *pHB, *pPool, *pT1, *pT2, *pT3;
    cudaGetSymbolAddress((void**)&pY,    g_y);
    cudaGetSymbolAddress((void**)&pZ,    g_z);
    cudaGetSymbolAddress((void**)&pHA,   g_hA);
    cudaGetSymbolAddress((void**)&pHB,   g_hB);
    cudaGetSymbolAddress((void**)&pPool, g_pool);
    cudaGetSymbolAddress((void**)&pT1,   g_t1);
    cudaGetSymbolAddress((void**)&pT2,   g_t2);
    cudaGetSymbolAddress((void**)&pT3,   g_t3);

    const int EB = (NE + 255) / 256;          // 3125
    const int MB = (NN + 127) / 128;          // 391
    const int WB = (NN * 32 + 255) / 256;     // 6250

    detect_kernel<<<1, 256>>>((const long long*)ei, (const long long*)bt);   // 0
    convert_kernel<<<EB, 256>>>(ei, bt);                                      // 1
    scan_kernel<<<1, 1024>>>();                                               // 2
    // gemm_fused for layer 1 depends only on x + weights: moved to launch
    // index 3 so the fixed ncu capture slot profiles it this round.
    gemm_fused<128><<<MB, 256>>>(x, W1l, W1r, b1l, pY, pZ);                   // 3 (profiled)
    fill_kernel<<<EB, 256>>>();                                               // 4

    aggregate_kernel<false><<<WB, 256>>>(pHA);

    // ---- layer 2 (K=64) ----
    gemm_fused<64><<<MB, 256>>>(pHA, W2l, W2r, b2l, pY, pZ);
    aggregate_kernel<false><<<WB, 256>>>(pHB);

    // ---- layer 3 (K=64) + pooling fused ----
    gemm_fused<64><<<MB, 256>>>(pHB, W3l, W3r, b3l, pY, pZ);
    aggregate_kernel<true><<<WB, 256>>>(nullptr);

    poolnorm_kernel<<<(NG * H + 255) / 256, 256>>>();

    // ---- MLP head (fused gemm+BN+tanh per layer, smem-staged A) ----
    head_kernel<64, 256><<<256, 256>>>(pPool, lin1_w, lin1_b, g1, be1, pT1);
    head_kernel<256, 128><<<128, 256>>>(pT1, lin2_w, lin2_b, g2, be2, pT2);
    head_kernel<128, 64><<<64, 256>>>(pT2, lin3_w, lin3_b, g3, be3, pT3);
    final_kernel<<<10, 256>>>(pT3, lin4_w, lin4_b, out);
}

// round 7
// speedup vs baseline: 1.0460x; 1.0460x over previous
#include <cuda_runtime.h>
#include <cuda_bf16.h>
#include <cstdint>
#include <math.h>

#define NN 50000
#define NE 800000
#define NG 256
#define H 64
#define BN_EPS 1e-5f

// ------------------------ device scratch (no allocs allowed) -----------------
__device__ int   g_src[NE];
__device__ int   g_dst[NE];
__device__ int   g_batch[NN];
__device__ int   g_cnt[NN];          // statically zero; re-zeroed by scan each run
__device__ int   g_rowstart[NN + 1];
__device__ int   g_cursor[NN];
__device__ float g_invcnt[NN];
__device__ int   g_csr_src[NE];
__device__ float g_y[NN * H];        // Y = A @ Wl
__device__ float g_z[NN * H];        // Z = A @ Wr + bias
__device__ float g_hA[NN * H];
__device__ float g_hB[NN * H];
__device__ float g_pacc[NG * H];     // statically zero; re-zeroed by poolnorm
__device__ float g_pcnt[NG];         // statically zero; re-zeroed by final_kernel
__device__ float g_pool[NG * H];
__device__ float g_t1[NG * 256];
__device__ float g_t2[NG * 128];
__device__ float g_t3[NG * 64];

// ---------------- convert + histogram (dtype probed per block) --------------
// Every block reads the SAME first 256 candidate int64 values -> identical,
// deterministic is64 decision everywhere; no separate detect launch.
__global__ void convert_kernel(const void* ei, const void* bt) {
    const long long* p64 = (const long long*)ei;
    long long probe = p64[threadIdx.x];
    int bad = (probe < 0 || probe >= NN) ? 1 : 0;
    bool is64 = (__syncthreads_or(bad) == 0);

    int i = blockIdx.x * blockDim.x + threadIdx.x;
    if (i < NE) {
        int s, d;
        if (is64) {
            s = (int)p64[i]; d = (int)p64[NE + i];
        } else {
            const int* p = (const int*)ei;
            s = p[i]; d = p[NE + i];
        }
        g_src[i] = s; g_dst[i] = d;
        atomicAdd(&g_cnt[d], 1);
    }
    if (i < NN) {
        if (is64) g_batch[i] = (int)((const long long*)bt)[i];
        else      g_batch[i] = ((const int*)bt)[i];
    }
}

// ------------------------ chunked shuffle scan (1 block, 1024 threads) ------
__global__ void scan_kernel() {
    const int C = (NN + 1023) / 1024;   // 49
    int tid = threadIdx.x;
    int base = tid * C;
    int s = 0;
#pragma unroll 7
    for (int j = 0; j < C; j++) {
        int idx = base + j;
        if (idx < NN) s += g_cnt[idx];
    }
    int lane = tid & 31, wid = tid >> 5;
    int v = s;
#pragma unroll
    for (int off = 1; off < 32; off <<= 1) {
        int t = __shfl_up_sync(0xffffffffu, v, off);
        if (lane >= off) v += t;
    }
    __shared__ int wsum[32];
    if (lane == 31) wsum[wid] = v;
    __syncthreads();
    if (wid == 0) {
        int w = wsum[lane];
#pragma unroll
        for (int off = 1; off < 32; off <<= 1) {
            int t = __shfl_up_sync(0xffffffffu, w, off);
            if (lane >= off) w += t;
        }
        wsum[lane] = w;
    }
    __syncthreads();
    int pref = v - s + (wid > 0 ? wsum[wid - 1] : 0);   // exclusive prefix
#pragma unroll 7
    for (int j = 0; j < C; j++) {
        int idx = base + j;
        if (idx < NN) {
            int c = g_cnt[idx];
            g_rowstart[idx] = pref;
            g_cursor[idx] = pref;
            g_invcnt[idx] = 1.0f / (float)max(c, 1);
            pref += c;
            g_cnt[idx] = 0;                     // reset for next replay
        }
    }
    if (tid == 0) g_rowstart[NN] = NE;
}

__global__ void fill_kernel() {
    int e = blockIdx.x * blockDim.x + threadIdx.x;
    if (e < NE) {
        int d = g_dst[e];
        int pos = atomicAdd(&g_cursor[d], 1);
        g_csr_src[pos] = g_src[e];
    }
}

// ------------------ cp.async helpers ----------------------------------------
__device__ __forceinline__ void cp_async16(void* smem_dst, const void* gmem_src, int src_bytes) {
    unsigned int dst = (unsigned int)__cvta_generic_to_shared(smem_dst);
    asm volatile("cp.async.cg.shared.global [%0], [%1], 16, %2;\n"
                 :: "r"(dst), "l"(gmem_src), "r"(src_bytes));
}
__device__ __forceinline__ void cp_commit() { asm volatile("cp.async.commit_group;\n"); }
__device__ __forceinline__ void cp_wait1()  { asm volatile("cp.async.wait_group 1;\n"); }
__device__ __forceinline__ void cp_wait0()  { asm volatile("cp.async.wait_group 0;\n"); }

// ------------------ fused dual GEMM: Y = A@Wl, Z = A@Wr + bias --------------
// W resident in SMEM (loaded once); A streamed in 32-k tiles through a 3-deep
// cp.async ring -> 1 sync per tile, loads overlap compute.
// dyn smem: Ws[K*128] + As[3][128*32] floats.
template <int K>
__launch_bounds__(256)
__global__ void gemm_fused(const float* __restrict__ A,
                           const float* __restrict__ Wl,
                           const float* __restrict__ Wr,
                           const float* __restrict__ bias,
                           float* __restrict__ Y, float* __restrict__ Z) {
    extern __shared__ float sm[];
    float* Ws = sm;                 // K * 128
    float* As = sm + K * 128;       // 3 * 4096
    const int tid = threadIdx.x;
    const int tr = tid >> 4, tc = tid & 15;
    const int m0 = blockIdx.x * 128;
    const int NT = K / 32;

    // W once: K*32 float4, K/8 per thread
#pragma unroll
    for (int i = 0; i < K / 8; i++) {
        int idx4 = i * 256 + tid;
        int r = idx4 >> 5, c = (idx4 & 31) * 4;
        float4 v = (c < 64) ? *(const float4*)&Wl[r * 64 + c]
                            : *(const float4*)&Wr[r * 64 + (c - 64)];
        *(float4*)&Ws[r * 128 + c] = v;
    }

    // prologue: tile 0
    {
#pragma unroll
        for (int i = 0; i < 4; i++) {
            int idx4 = i * 256 + tid;
            int r = idx4 >> 3, c4 = idx4 & 7;
            int gr = m0 + r;
            cp_async16(&As[r * 32 + c4 * 4], &A[(size_t)gr * K + c4 * 4],
                       (gr < NN) ? 16 : 0);
        }
        cp_commit();
    }

    float acc[8][8];
#pragma unroll
    for (int r = 0; r < 8; r++)
#pragma unroll
        for (int c = 0; c < 8; c++) acc[r][c] = 0.f;

    for (int t = 0; t < NT; t++) {
        if (t + 1 < NT) {
            int buf = (t + 1) % 3;
            int k0 = (t + 1) * 32;
#pragma unroll
            for (int i = 0; i < 4; i++) {
                int idx4 = i * 256 + tid;
                int r = idx4 >> 3, c4 = idx4 & 7;
                int gr = m0 + r;
                cp_async16(&As[buf * 4096 + r * 32 + c4 * 4],
                           &A[(size_t)gr * K + k0 + c4 * 4],
                           (gr < NN) ? 16 : 0);
            }
            cp_commit();
            cp_wait1();
        } else {
            cp_wait0();
        }
        __syncthreads();

        const float* At = &As[(t % 3) * 4096];
        const float* Wt = &Ws[t * 32 * 128];
#pragma unroll 8
        for (int k = 0; k < 32; k++) {
            float a[8], w[8];
#pragma unroll
            for (int r = 0; r < 8; r++) a[r] = At[(tr * 8 + r) * 32 + k];
            float4 w0 = *(const float4*)&Wt[k * 128 + tc * 8];
            float4 w1 = *(const float4*)&Wt[k * 128 + tc * 8 + 4];
            w[0] = w0.x; w[1] = w0.y; w[2] = w0.z; w[3] = w0.w;
            w[4] = w1.x; w[5] = w1.y; w[6] = w1.z; w[7] = w1.w;
#pragma unroll
            for (int r = 0; r < 8; r++)
#pragma unroll
                for (int c = 0; c < 8; c++) acc[r][c] = fmaf(a[r], w[c], acc[r][c]);
        }
    }

    bool isZ = (tc >= 8);
    int col = (tc & 7) * 8;
    float bv[8];
#pragma unroll
    for (int c = 0; c < 8; c++) bv[c] = isZ ? bias[col + c] : 0.f;
    float* O = isZ ? Z : Y;
#pragma unroll
    for (int r = 0; r < 8; r++) {
        int gr = m0 + tr * 8 + r;
        if (gr < NN) {
            float4 v0, v1;
            v0.x = acc[r][0] + bv[0]; v0.y = acc[r][1] + bv[1];
            v0.z = acc[r][2] + bv[2]; v0.w = acc[r][3] + bv[3];
            v1.x = acc[r][4] + bv[4]; v1.y = acc[r][5] + bv[5];
            v1.z = acc[r][6] + bv[6]; v1.w = acc[r][7] + bv[7];
            *(float4*)&O[gr * 64 + col] = v0;
            *(float4*)&O[gr * 64 + col + 4] = v1;
        }
    }
}

// -------- aggregation + combine: h = ic * sum(Y[src]) + Z  (warp/node) ------
template <bool POOL>
__global__ void aggregate_kernel(float* __restrict__ Hout) {
    int w = (blockIdx.x * blockDim.x + threadIdx.x) >> 5;
    int lane = threadIdx.x & 31;
    if (w >= NN) return;
    int s0 = g_rowstart[w], s1 = g_rowstart[w + 1];
    float ax = 0.f, ay = 0.f;
    for (int base = s0; base < s1; base += 32) {
        int rem = s1 - base;
        int idx = (lane < rem) ? g_csr_src[base + lane] : 0;
        int m = rem < 32 ? rem : 32;
#pragma unroll 4
        for (int j = 0; j < m; j++) {
            int s = __shfl_sync(0xffffffffu, idx, j);
            float2 v = *(const float2*)&g_y[s * 64 + lane * 2];
            ax += v.x; ay += v.y;
        }
    }
    float ic = g_invcnt[w];
    float2 z = *(const float2*)&g_z[w * 64 + lane * 2];
    float ox = ax * ic + z.x, oy = ay * ic + z.y;
    if (POOL) {
        int g = g_batch[w];
        atomicAdd(&g_pacc[g * 64 + lane * 2 + 0], ox);
        atomicAdd(&g_pacc[g * 64 + lane * 2 + 1], oy);
        if (lane == 0) atomicAdd(&g_pcnt[g], 1.f);
    } else {
        float2 o; o.x = ox; o.y = oy;
        *(float2*)&Hout[w * 64 + lane * 2] = o;
    }
}

// normalize pool; re-zero pacc for next replay (pcnt zeroed in final_kernel)
__global__ void poolnorm_kernel() {
    int i = blockIdx.x * blockDim.x + threadIdx.x;
    if (i < NG * H) {
        float c = g_pcnt[i >> 6];
        g_pool[i] = g_pacc[i] / fmaxf(c, 1.f);
        g_pacc[i] = 0.f;
    }
}

// ---------------- fused head layer: X = tanh(BN(A@W + b)) -------------------
template <int K, int N>
__launch_bounds__(256)
__global__ void head_kernel(const float* __restrict__ A, const float* __restrict__ W,
                            const float* __restrict__ b,
                            const float* __restrict__ gam, const float* __restrict__ bet,
                            float* __restrict__ X) {
    __shared__ float As[256 * 33];
    int j = blockIdx.x, i = threadIdx.x;
    float acc = b[j];
    for (int k0 = 0; k0 < K; k0 += 32) {
#pragma unroll
        for (int t = 0; t < 32; t++) {
            int idx = t * 256 + i;
            int r = idx >> 5, c = idx & 31;
            As[r * 33 + c] = A[r * K + k0 + c];
        }
        __syncthreads();
#pragma unroll
        for (int kk = 0; kk < 32; kk++)
            acc = fmaf(As[i * 33 + kk], W[(k0 + kk) * N + j], acc);
        __syncthreads();
    }
    __shared__ float red[256];
    red[i] = acc;
    __syncthreads();
    for (int off = 128; off > 0; off >>= 1) {
        if (i < off) red[i] += red[i + off];
        __syncthreads();
    }
    float mean = red[0] * (1.f / 256.f);
    __syncthreads();
    float d = acc - mean;
    red[i] = d * d;
    __syncthreads();
    for (int off = 128; off > 0; off >>= 1) {
        if (i < off) red[i] += red[i + off];
        __syncthreads();
    }
    float var = red[0] * (1.f / 256.f);
    X[i * N + j] = tanhf(d * rsqrtf(var + BN_EPS) * gam[j] + bet[j]);
}

// final linear (no BN); also re-zeroes g_pcnt for the next replay
__launch_bounds__(256)
__global__ void final_kernel(const float* __restrict__ A, const float* __restrict__ W,
                             const float* __restrict__ b, float* __restrict__ out) {
    __shared__ float As[256 * 33];
    int j = blockIdx.x, i = threadIdx.x;   // 10 blocks x 256 rows
    float acc = b[j];
    for (int k0 = 0; k0 < 64; k0 += 32) {
#pragma unroll
        for (int t = 0; t < 32; t++) {
            int idx = t * 256 + i;
            int r = idx >> 5, c = idx & 31;
            As[r * 33 + c] = A[r * 64 + k0 + c];
        }
        __syncthreads();
#pragma unroll
        for (int kk = 0; kk < 32; kk++)
            acc = fmaf(As[i * 33 + kk], W[(k0 + kk) * 10 + j], acc);
        __syncthreads();
    }
    out[i * 10 + j] = acc;
    if (j == 0) g_pcnt[i] = 0.f;
}

// ------------------------ launch --------------------------------------------
extern "C" void kernel_launch(void* const* d_in, const int* in_sizes, int n_in,
                              void* d_out, int out_size) {
    const float* x      = (const float*)d_in[0];
    const void*  ei     = d_in[1];
    const void*  bt     = d_in[2];
    const float* W1l    = (const float*)d_in[3];
    const float* b1l    = (const float*)d_in[4];
    const float* W1r    = (const float*)d_in[5];
    const float* W2l    = (const float*)d_in[6];
    const float* b2l    = (const float*)d_in[7];
    const float* W2r    = (const float*)d_in[8];
    const float* W3l    = (const float*)d_in[9];
    const float* b3l    = (const float*)d_in[10];
    const float* W3r    = (const float*)d_in[11];
    const float* lin1_w = (const float*)d_in[12];
    const float* lin1_b = (const float*)d_in[13];
    const float* g1     = (const float*)d_in[14];
    const float* be1    = (const float*)d_in[15];
    const float* lin2_w = (const float*)d_in[16];
    const float* lin2_b = (const float*)d_in[17];
    const float* g2     = (const float*)d_in[18];
    const float* be2    = (const float*)d_in[19];
    const float* lin3_w = (const float*)d_in[20];
    const float* lin3_b = (const float*)d_in[21];
    const float* g3     = (const float*)d_in[22];
    const float* be3    = (const float*)d_in[23];
    const float* lin4_w = (const float*)d_in[24];
    const float* lin4_b = (const float*)d_in[25];
    float* out = (float*)d_out;

    float *pY, *pZ, *pHA, *pHB, *pPool, *pT1, *pT2, *pT3;
    cudaGetSymbolAddress((void**)&pY,    g_y);
    cudaGetSymbolAddress((void**)&pZ,    g_z);
    cudaGetSymbolAddress((void**)&pHA,   g_hA);
    cudaGetSymbolAddress((void**)&pHB,   g_hB);
    cudaGetSymbolAddress((void**)&pPool, g_pool);
    cudaGetSymbolAddress((void**)&pT1,   g_t1);
    cudaGetSymbolAddress((void**)&pT2,   g_t2);
    cudaGetSymbolAddress((void**)&pT3,   g_t3);

    const int SM128 = (128 * 128 + 3 * 128 * 32) * 4;   // 114688 B
    const int SM64  = (64 * 128 + 3 * 128 * 32) * 4;    // 81920 B
    cudaFuncSetAttribute(gemm_fused<128>, cudaFuncAttributeMaxDynamicSharedMemorySize, SM128);
    cudaFuncSetAttribute(gemm_fused<64>,  cudaFuncAttributeMaxDynamicSharedMemorySize, SM64);

    const int EB = (NE + 255) / 256;          // 3125
    const int MB = (NN + 127) / 128;          // 391
    const int WB = (NN * 32 + 255) / 256;     // 6250

    convert_kernel<<<EB, 256>>>(ei, bt);                                      // 0
    scan_kernel<<<1, 1024>>>();                                               // 1
    fill_kernel<<<EB, 256>>>();                                               // 2
    gemm_fused<128><<<MB, 256, SM128>>>(x, W1l, W1r, b1l, pY, pZ);            // 3 (profiled)
    aggregate_kernel<false><<<WB, 256>>>(pHA);

    // ---- layer 2 (K=64) ----
    gemm_fused<64><<<MB, 256, SM64>>>(pHA, W2l, W2r, b2l, pY, pZ);
    aggregate_kernel<false><<<WB, 256>>>(pHB);

    // ---- layer 3 (K=64) + pooling fused ----
    gemm_fused<64><<<MB, 256, SM64>>>(pHB, W3l, W3r, b3l, pY, pZ);
    aggregate_kernel<true><<<WB, 256>>>(nullptr);

    poolnorm_kernel<<<(NG * H + 255) / 256, 256>>>();

    // ---- MLP head (fused gemm+BN+tanh per layer, smem-staged A) ----
    head_kernel<64, 256><<<256, 256>>>(pPool, lin1_w, lin1_b, g1, be1, pT1);
    head_kernel<256, 128><<<128, 256>>>(pT1, lin2_w, lin2_b, g2, be2, pT2);
    head_kernel<128, 64><<<64, 256>>>(pT2, lin3_w, lin3_b, g3, be3, pT3);
    final_kernel<<<10, 256>>>(pT3, lin4_w, lin4_b, out);
}

// round 9
// speedup vs baseline: 1.0514x; 1.0051x over previous
#include <cuda_runtime.h>
#include <cuda_bf16.h>
#include <cstdint>
#include <math.h>

#define NN 50000
#define NE 800000
#define NG 256
#define H 64
#define BN_EPS 1e-5f

// ------------------------ device scratch (no allocs allowed) -----------------
__device__ int   g_src[NE];
__device__ int   g_dst[NE];
__device__ int   g_batch[NN];
__device__ int   g_cnt[NN];          // statically zero; re-zeroed by scan each run
__device__ int   g_rowstart[NN + 1];
__device__ int   g_cursor[NN];
__device__ float g_invcnt[NN];
__device__ int   g_csr_src[NE];
__device__ float g_y[NN * H];        // Y = A @ Wl
__device__ float g_z[NN * H];        // Z = A @ Wr + bias
__device__ float g_hA[NN * H];
__device__ float g_hB[NN * H];
__device__ float g_pacc[NG * H];     // statically zero; re-zeroed by poolnorm
__device__ float g_pcnt[NG];         // statically zero; re-zeroed by final_kernel
__device__ float g_pool[NG * H];
__device__ float g_t1[NG * 256];
__device__ float g_t2[NG * 128];
__device__ float g_t3[NG * 64];

// ---------------- f32x2 packed-FMA helpers (sm_10x FFMA2) --------------------
__device__ __forceinline__ unsigned long long pack2(float lo, float hi) {
    unsigned long long r;
    asm("mov.b64 %0, {%1, %2};" : "=l"(r) : "f"(lo), "f"(hi));
    return r;
}
__device__ __forceinline__ void unpack2(unsigned long long v, float& lo, float& hi) {
    asm("mov.b64 {%0, %1}, %2;" : "=f"(lo), "=f"(hi) : "l"(v));
}
__device__ __forceinline__ void fma2(unsigned long long& d, unsigned long long a,
                                     unsigned long long b) {
    asm("fma.rn.f32x2 %0, %1, %2, %0;" : "+l"(d) : "l"(a), "l"(b));
}

// ---------------- convert + histogram (dtype probed per block) --------------
__global__ void convert_kernel(const void* ei, const void* bt) {
    const long long* p64 = (const long long*)ei;
    long long probe = p64[threadIdx.x];
    int bad = (probe < 0 || probe >= NN) ? 1 : 0;
    bool is64 = (__syncthreads_or(bad) == 0);

    int i = blockIdx.x * blockDim.x + threadIdx.x;
    if (i < NE) {
        int s, d;
        if (is64) {
            s = (int)p64[i]; d = (int)p64[NE + i];
        } else {
            const int* p = (const int*)ei;
            s = p[i]; d = p[NE + i];
        }
        g_src[i] = s; g_dst[i] = d;
        atomicAdd(&g_cnt[d], 1);
    }
    if (i < NN) {
        if (is64) g_batch[i] = (int)((const long long*)bt)[i];
        else      g_batch[i] = ((const int*)bt)[i];
    }
}

// ------------------------ chunked shuffle scan (1 block, 1024 threads) ------
__global__ void scan_kernel() {
    const int C = (NN + 1023) / 1024;   // 49
    int tid = threadIdx.x;
    int base = tid * C;
    int s = 0;
#pragma unroll 7
    for (int j = 0; j < C; j++) {
        int idx = base + j;
        if (idx < NN) s += g_cnt[idx];
    }
    int lane = tid & 31, wid = tid >> 5;
    int v = s;
#pragma unroll
    for (int off = 1; off < 32; off <<= 1) {
        int t = __shfl_up_sync(0xffffffffu, v, off);
        if (lane >= off) v += t;
    }
    __shared__ int wsum[32];
    if (lane == 31) wsum[wid] = v;
    __syncthreads();
    if (wid == 0) {
        int w = wsum[lane];
#pragma unroll
        for (int off = 1; off < 32; off <<= 1) {
            int t = __shfl_up_sync(0xffffffffu, w, off);
            if (lane >= off) w += t;
        }
        wsum[lane] = w;
    }
    __syncthreads();
    int pref = v - s + (wid > 0 ? wsum[wid - 1] : 0);   // exclusive prefix
#pragma unroll 7
    for (int j = 0; j < C; j++) {
        int idx = base + j;
        if (idx < NN) {
            int c = g_cnt[idx];
            g_rowstart[idx] = pref;
            g_cursor[idx] = pref;
            g_invcnt[idx] = 1.0f / (float)max(c, 1);
            pref += c;
            g_cnt[idx] = 0;                     // reset for next replay
        }
    }
    if (tid == 0) g_rowstart[NN] = NE;
}

__global__ void fill_kernel() {
    int e = blockIdx.x * blockDim.x + threadIdx.x;
    if (e < NE) {
        int d = g_dst[e];
        int pos = atomicAdd(&g_cursor[d], 1);
        g_csr_src[pos] = g_src[e];
    }
}

// ------------------ fused dual GEMM: Y = A@Wl, Z = A@Wr + bias --------------
// f32x2 packed FMA. A tile staged k-major (Ast[k][row], row-pitch 130) so a
// row-pair is one aligned LDS.64, already packed for FFMA2. Rows are paired
// in the accumulator; columns run free. 128x128 output tile (Y|Z), 256 thr.
#define AP 130
template <int K>
__launch_bounds__(256, 2)
__global__ void gemm_fused(const float* __restrict__ A,
                           const float* __restrict__ Wl,
                           const float* __restrict__ Wr,
                           const float* __restrict__ bias,
                           float* __restrict__ Y, float* __restrict__ Z) {
    __shared__ float Ast[32 * AP];      // k-major A tile
    __shared__ float Ws[32 * 128];      // Ws[k][col]; col<64 Wl, col>=64 Wr
    const int tid = threadIdx.x;
    const int tr = tid >> 4, tc = tid & 15;
    const int m0 = blockIdx.x * 128;

    unsigned long long acc[4][8];       // [row-pair][col]; 8 rows x 8 cols
#pragma unroll
    for (int p = 0; p < 4; p++)
#pragma unroll
        for (int c = 0; c < 8; c++) acc[p][c] = 0ull;

    for (int k0 = 0; k0 < K; k0 += 32) {
        // A tile transposed into k-major: 4 float4 loads/thread, 16 STS.32
#pragma unroll
        for (int i = 0; i < 4; i++) {
            int idx4 = i * 256 + tid;
            int r = idx4 >> 3, c4 = idx4 & 7;
            int gr = m0 + r;
            float4 v = make_float4(0.f, 0.f, 0.f, 0.f);
            if (gr < NN) v = *(const float4*)&A[(size_t)gr * K + k0 + c4 * 4];
            Ast[(c4 * 4 + 0) * AP + r] = v.x;
            Ast[(c4 * 4 + 1) * AP + r] = v.y;
            Ast[(c4 * 4 + 2) * AP + r] = v.z;
            Ast[(c4 * 4 + 3) * AP + r] = v.w;
        }
        // W tile: coalesced float4
#pragma unroll
        for (int i = 0; i < 4; i++) {
            int idx4 = i * 256 + tid;
            int r = idx4 >> 5, c = (idx4 & 31) * 4;
            float4 v = (c < 64) ? *(const float4*)&Wl[(k0 + r) * 64 + c]
                                : *(const float4*)&Wr[(k0 + r) * 64 + (c - 64)];
            *(float4*)&Ws[r * 128 + c] = v;
        }
        __syncthreads();
#pragma unroll 4
        for (int k = 0; k < 32; k++) {
            unsigned long long a[4];
#pragma unroll
            for (int p = 0; p < 4; p++)
                a[p] = *(const unsigned long long*)&Ast[k * AP + tr * 8 + 2 * p];
            float4 w0 = *(const float4*)&Ws[k * 128 + tc * 8];
            float4 w1 = *(const float4*)&Ws[k * 128 + tc * 8 + 4];
            unsigned long long wd[8];
            wd[0] = pack2(w0.x, w0.x); wd[1] = pack2(w0.y, w0.y);
            wd[2] = pack2(w0.z, w0.z); wd[3] = pack2(w0.w, w0.w);
            wd[4] = pack2(w1.x, w1.x); wd[5] = pack2(w1.y, w1.y);
            wd[6] = pack2(w1.z, w1.z); wd[7] = pack2(w1.w, w1.w);
#pragma unroll
            for (int p = 0; p < 4; p++)
#pragma unroll
                for (int c = 0; c < 8; c++) fma2(acc[p][c], a[p], wd[c]);
        }
        __syncthreads();
    }

    bool isZ = (tc >= 8);
    int col = (tc & 7) * 8;
    float bv[8];
#pragma unroll
    for (int c = 0; c < 8; c++) bv[c] = isZ ? bias[col + c] : 0.f;
    float* O = isZ ? Z : Y;
#pragma unroll
    for (int p = 0; p < 4; p++) {
        float lo[8], hi[8];
#pragma unroll
        for (int c = 0; c < 8; c++) unpack2(acc[p][c], lo[c], hi[c]);
        int r0 = m0 + tr * 8 + 2 * p;
        if (r0 < NN) {
            float4 v0 = make_float4(lo[0] + bv[0], lo[1] + bv[1], lo[2] + bv[2], lo[3] + bv[3]);
            float4 v1 = make_float4(lo[4] + bv[4], lo[5] + bv[5], lo[6] + bv[6], lo[7] + bv[7]);
            *(float4*)&O[r0 * 64 + col] = v0;
            *(float4*)&O[r0 * 64 + col + 4] = v1;
        }
        if (r0 + 1 < NN) {
            float4 v0 = make_float4(hi[0] + bv[0], hi[1] + bv[1], hi[2] + bv[2], hi[3] + bv[3]);
            float4 v1 = make_float4(hi[4] + bv[4], hi[5] + bv[5], hi[6] + bv[6], hi[7] + bv[7]);
            *(float4*)&O[(r0 + 1) * 64 + col] = v0;
            *(float4*)&O[(r0 + 1) * 64 + col + 4] = v1;
        }
    }
}

// -------- aggregation + combine: h = ic * sum(Y[src]) + Z  (warp/node) ------
template <bool POOL>
__global__ void aggregate_kernel(float* __restrict__ Hout) {
    int w = (blockIdx.x * blockDim.x + threadIdx.x) >> 5;
    int lane = threadIdx.x & 31;
    if (w >= NN) return;
    int s0 = g_rowstart[w], s1 = g_rowstart[w + 1];
    float ax = 0.f, ay = 0.f;
    for (int base = s0; base < s1; base += 32) {
        int rem = s1 - base;
        int idx = (lane < rem) ? g_csr_src[base + lane] : 0;
        int m = rem < 32 ? rem : 32;
#pragma unroll 4
        for (int j = 0; j < m; j++) {
            int s = __shfl_sync(0xffffffffu, idx, j);
            float2 v = *(const float2*)&g_y[s * 64 + lane * 2];
            ax += v.x; ay += v.y;
        }
    }
    float ic = g_invcnt[w];
    float2 z = *(const float2*)&g_z[w * 64 + lane * 2];
    float ox = ax * ic + z.x, oy = ay * ic + z.y;
    if (POOL) {
        int g = g_batch[w];
        atomicAdd(&g_pacc[g * 64 + lane * 2 + 0], ox);
        atomicAdd(&g_pacc[g * 64 + lane * 2 + 1], oy);
        if (lane == 0) atomicAdd(&g_pcnt[g], 1.f);
    } else {
        float2 o; o.x = ox; o.y = oy;
        *(float2*)&Hout[w * 64 + lane * 2] = o;
    }
}

// normalize pool; re-zero pacc for next replay (pcnt zeroed in final_kernel)
__global__ void poolnorm_kernel() {
    int i = blockIdx.x * blockDim.x + threadIdx.x;
    if (i < NG * H) {
        float c = g_pcnt[i >> 6];
        g_pool[i] = g_pacc[i] / fmaxf(c, 1.f);
        g_pacc[i] = 0.f;
    }
}

// ---------------- fused head layer: X = tanh(BN(A@W + b)) -------------------
template <int K, int N>
__launch_bounds__(256)
__global__ void head_kernel(const float* __restrict__ A, const float* __restrict__ W,
                            const float* __restrict__ b,
                            const float* __restrict__ gam, const float* __restrict__ bet,
                            float* __restrict__ X) {
    __shared__ float As[256 * 33];
    int j = blockIdx.x, i = threadIdx.x;
    float acc = b[j];
    for (int k0 = 0; k0 < K; k0 += 32) {
#pragma unroll
        for (int t = 0; t < 32; t++) {
            int idx = t * 256 + i;
            int r = idx >> 5, c = idx & 31;
            As[r * 33 + c] = A[r * K + k0 + c];
        }
        __syncthreads();
#pragma unroll
        for (int kk = 0; kk < 32; kk++)
            acc = fmaf(As[i * 33 + kk], W[(k0 + kk) * N + j], acc);
        __syncthreads();
    }
    __shared__ float red[256];
    red[i] = acc;
    __syncthreads();
    for (int off = 128; off > 0; off >>= 1) {
        if (i < off) red[i] += red[i + off];
        __syncthreads();
    }
    float mean = red[0] * (1.f / 256.f);
    __syncthreads();
    float d = acc - mean;
    red[i] = d * d;
    __syncthreads();
    for (int off = 128; off > 0; off >>= 1) {
        if (i < off) red[i] += red[i + off];
        __syncthreads();
    }
    float var = red[0] * (1.f / 256.f);
    X[i * N + j] = tanhf(d * rsqrtf(var + BN_EPS) * gam[j] + bet[j]);
}

// final linear (no BN); also re-zeroes g_pcnt for the next replay
__launch_bounds__(256)
__global__ void final_kernel(const float* __restrict__ A, const float* __restrict__ W,
                             const float* __restrict__ b, float* __restrict__ out) {
    __shared__ float As[256 * 33];
    int j = blockIdx.x, i = threadIdx.x;   // 10 blocks x 256 rows
    float acc = b[j];
    for (int k0 = 0; k0 < 64; k0 += 32) {
#pragma unroll
        for (int t = 0; t < 32; t++) {
            int idx = t * 256 + i;
            int r = idx >> 5, c = idx & 31;
            As[r * 33 + c] = A[r * 64 + k0 + c];
        }
        __syncthreads();
#pragma unroll
        for (int kk = 0; kk < 32; kk++)
            acc = fmaf(As[i * 33 + kk], W[(k0 + kk) * 10 + j], acc);
        __syncthreads();
    }
    out[i * 10 + j] = acc;
    if (j == 0) g_pcnt[i] = 0.f;
}

// ------------------------ launch --------------------------------------------
extern "C" void kernel_launch(void* const* d_in, const int* in_sizes, int n_in,
                              void* d_out, int out_size) {
    const float* x      = (const float*)d_in[0];
    const void*  ei     = d_in[1];
    const void*  bt     = d_in[2];
    const float* W1l    = (const float*)d_in[3];
    const float* b1l    = (const float*)d_in[4];
    const float* W1r    = (const float*)d_in[5];
    const float* W2l    = (const float*)d_in[6];
    const float* b2l    = (const float*)d_in[7];
    const float* W2r    = (const float*)d_in[8];
    const float* W3l    = (const float*)d_in[9];
    const float* b3l    = (const float*)d_in[10];
    const float* W3r    = (const float*)d_in[11];
    const float* lin1_w = (const float*)d_in[12];
    const float* lin1_b = (const float*)d_in[13];
    const float* g1     = (const float*)d_in[14];
    const float* be1    = (const float*)d_in[15];
    const float* lin2_w = (const float*)d_in[16];
    const float* lin2_b = (const float*)d_in[17];
    const float* g2     = (const float*)d_in[18];
    const float* be2    = (const float*)d_in[19];
    const float* lin3_w = (const float*)d_in[20];
    const float* lin3_b = (const float*)d_in[21];
    const float* g3     = (const float*)d_in[22];
    const float* be3    = (const float*)d_in[23];
    const float* lin4_w = (const float*)d_in[24];
    const float* lin4_b = (const float*)d_in[25];
    float* out = (float*)d_out;

    float *pY, *pZ, *pHA, *pHB, *pPool, *pT1, *pT2, *pT3;
    cudaGetSymbolAddress((void**)&pY,    g_y);
    cudaGetSymbolAddress((void**)&pZ,    g_z);
    cudaGetSymbolAddress((void**)&pHA,   g_hA);
    cudaGetSymbolAddress((void**)&pHB,   g_hB);
    cudaGetSymbolAddress((void**)&pPool, g_pool);
    cudaGetSymbolAddress((void**)&pT1,   g_t1);
    cudaGetSymbolAddress((void**)&pT2,   g_t2);
    cudaGetSymbolAddress((void**)&pT3,   g_t3);

    const int EB = (NE + 255) / 256;          // 3125
    const int MB = (NN + 127) / 128;          // 391
    const int WB = (NN * 32 + 255) / 256;     // 6250

    convert_kernel<<<EB, 256>>>(ei, bt);                                      // 0
    scan_kernel<<<1, 1024>>>();                                               // 1
    fill_kernel<<<EB, 256>>>();                                               // 2
    gemm_fused<128><<<MB, 256>>>(x, W1l, W1r, b1l, pY, pZ);                   // 3 (profiled)
    aggregate_kernel<false><<<WB, 256>>>(pHA);

    // ---- layer 2 (K=64) ----
    gemm_fused<64><<<MB, 256>>>(pHA, W2l, W2r, b2l, pY, pZ);
    aggregate_kernel<false><<<WB, 256>>>(pHB);

    // ---- layer 3 (K=64) + pooling fused ----
    gemm_fused<64><<<MB, 256>>>(pHB, W3l, W3r, b3l, pY, pZ);
    aggregate_kernel<true><<<WB, 256>>>(nullptr);

    poolnorm_kernel<<<(NG * H + 255) / 256, 256>>>();

    // ---- MLP head (fused gemm+BN+tanh per layer, smem-staged A) ----
    head_kernel<64, 256><<<256, 256>>>(pPool, lin1_w, lin1_b, g1, be1, pT1);
    head_kernel<256, 128><<<128, 256>>>(pT1, lin2_w, lin2_b, g2, be2, pT2);
    head_kernel<128, 64><<<64, 256>>>(pT2, lin3_w, lin3_b, g3, be3, pT3);
    final_kernel<<<10, 256>>>(pT3, lin4_w, lin4_b, out);
}

// round 10
// speedup vs baseline: 1.1205x; 1.0658x over previous
#include <cuda_runtime.h>
#include <cuda_bf16.h>
#include <cstdint>
#include <math.h>

#define NN 50000
#define NE 800000
#define NG 256
#define H 64
#define BN_EPS 1e-5f

// ------------------------ device scratch (no allocs allowed) -----------------
__device__ int   g_src[NE];
__device__ int   g_dst[NE];
__device__ int   g_batch[NN];
__device__ int   g_cnt[NN];          // statically zero; re-zeroed by scan each run
__device__ int   g_rowstart[NN + 1];
__device__ int   g_cursor[NN];
__device__ float g_invcnt[NN];
__device__ int   g_csr_src[NE];
__device__ float g_y[NN * H];        // Y = A @ Wl
__device__ float g_z[NN * H];        // Z = A @ Wr + bias
__device__ float g_hA[NN * H];
__device__ float g_hB[NN * H];
__device__ float g_pacc[NG * H];     // statically zero; re-zeroed by final_kernel
__device__ float g_pcnt[NG];         // statically zero; re-zeroed by final_kernel
__device__ float g_t1[NG * 256];
__device__ float g_t2[NG * 128];
__device__ float g_t3[NG * 64];

// ---------------- f32x2 packed-FMA helpers (sm_10x FFMA2) --------------------
__device__ __forceinline__ unsigned long long pack2(float lo, float hi) {
    unsigned long long r;
    asm("mov.b64 %0, {%1, %2};" : "=l"(r) : "f"(lo), "f"(hi));
    return r;
}
__device__ __forceinline__ void unpack2(unsigned long long v, float& lo, float& hi) {
    asm("mov.b64 {%0, %1}, %2;" : "=f"(lo), "=f"(hi) : "l"(v));
}
__device__ __forceinline__ void fma2(unsigned long long& d, unsigned long long a,
                                     unsigned long long b) {
    asm("fma.rn.f32x2 %0, %1, %2, %0;" : "+l"(d) : "l"(a), "l"(b));
}

// ---------------- convert + histogram (dtype probed per block) --------------
__global__ void convert_kernel(const void* ei, const void* bt) {
    const long long* p64 = (const long long*)ei;
    long long probe = p64[threadIdx.x];
    int bad = (probe < 0 || probe >= NN) ? 1 : 0;
    bool is64 = (__syncthreads_or(bad) == 0);

    int i = blockIdx.x * blockDim.x + threadIdx.x;
    if (i < NE) {
        int s, d;
        if (is64) {
            s = (int)p64[i]; d = (int)p64[NE + i];
        } else {
            const int* p = (const int*)ei;
            s = p[i]; d = p[NE + i];
        }
        g_src[i] = s; g_dst[i] = d;
        atomicAdd(&g_cnt[d], 1);
    }
    if (i < NN) {
        if (is64) g_batch[i] = (int)((const long long*)bt)[i];
        else      g_batch[i] = ((const int*)bt)[i];
    }
}

// ------------------------ chunked shuffle scan (1 block, 1024 threads) ------
__global__ void scan_kernel() {
    const int C = (NN + 1023) / 1024;   // 49
    int tid = threadIdx.x;
    int base = tid * C;
    int s = 0;
#pragma unroll 7
    for (int j = 0; j < C; j++) {
        int idx = base + j;
        if (idx < NN) s += g_cnt[idx];
    }
    int lane = tid & 31, wid = tid >> 5;
    int v = s;
#pragma unroll
    for (int off = 1; off < 32; off <<= 1) {
        int t = __shfl_up_sync(0xffffffffu, v, off);
        if (lane >= off) v += t;
    }
    __shared__ int wsum[32];
    if (lane == 31) wsum[wid] = v;
    __syncthreads();
    if (wid == 0) {
        int w = wsum[lane];
#pragma unroll
        for (int off = 1; off < 32; off <<= 1) {
            int t = __shfl_up_sync(0xffffffffu, w, off);
            if (lane >= off) w += t;
        }
        wsum[lane] = w;
    }
    __syncthreads();
    int pref = v - s + (wid > 0 ? wsum[wid - 1] : 0);   // exclusive prefix
#pragma unroll 7
    for (int j = 0; j < C; j++) {
        int idx = base + j;
        if (idx < NN) {
            int c = g_cnt[idx];
            g_rowstart[idx] = pref;
            g_cursor[idx] = pref;
            g_invcnt[idx] = 1.0f / (float)max(c, 1);
            pref += c;
            g_cnt[idx] = 0;                     // reset for next replay
        }
    }
    if (tid == 0) g_rowstart[NN] = NE;
}

__global__ void fill_kernel() {
    int e = blockIdx.x * blockDim.x + threadIdx.x;
    if (e < NE) {
        int d = g_dst[e];
        int pos = atomicAdd(&g_cursor[d], 1);
        g_csr_src[pos] = g_src[e];
    }
}

// ------------------ fused dual GEMM: Y = A@Wl, Z = A@Wr + bias --------------
// FFMA2 with zero inner-loop ALU: A staged k-major (row-pair = 1 aligned
// LDS.64), W staged PRE-DUPLICATED (each value as a (v,v) 8-byte pair).
// Wd slot pitch = 18 floats so the 16 lane addresses hit 16 disjoint
// bank-pairs -> conflict-free LDS.64. Inner loop/k: 12 LDS.64 + 32 FFMA2.
#define AP 130
#define WDP 288   // 16 slots * 18 floats
template <int K>
__launch_bounds__(256, 2)
__global__ void gemm_fused(const float* __restrict__ A,
                           const float* __restrict__ Wl,
                           const float* __restrict__ Wr,
                           const float* __restrict__ bias,
                           float* __restrict__ Y, float* __restrict__ Z) {
    extern __shared__ float sm[];
    float* Ast = sm;                 // 32 * AP  (k-major A tile)
    float* Wd  = sm + 32 * AP;       // 32 * WDP (dup-packed W tile)
    const int tid = threadIdx.x;
    const int tr = tid >> 4, tc = tid & 15;
    const int m0 = blockIdx.x * 128;

    unsigned long long acc[4][8];
#pragma unroll
    for (int p = 0; p < 4; p++)
#pragma unroll
        for (int c = 0; c < 8; c++) acc[p][c] = 0ull;

    for (int k0 = 0; k0 < K; k0 += 32) {
        // A tile -> k-major
#pragma unroll
        for (int i = 0; i < 4; i++) {
            int idx4 = i * 256 + tid;
            int r = idx4 >> 3, c4 = idx4 & 7;
            int gr = m0 + r;
            float4 v = make_float4(0.f, 0.f, 0.f, 0.f);
            if (gr < NN) v = *(const float4*)&A[(size_t)gr * K + k0 + c4 * 4];
            Ast[(c4 * 4 + 0) * AP + r] = v.x;
            Ast[(c4 * 4 + 1) * AP + r] = v.y;
            Ast[(c4 * 4 + 2) * AP + r] = v.z;
            Ast[(c4 * 4 + 3) * AP + r] = v.w;
        }
        // W tile -> duplicated pairs: col cg at offset k*WDP + (cg>>3)*18 + (cg&7)*2
#pragma unroll
        for (int i = 0; i < 4; i++) {
            int idx4 = i * 256 + tid;
            int r = idx4 >> 5, c = (idx4 & 31) * 4;
            float4 v = (c < 64) ? *(const float4*)&Wl[(k0 + r) * 64 + c]
                                : *(const float4*)&Wr[(k0 + r) * 64 + (c - 64)];
            float vv[4] = {v.x, v.y, v.z, v.w};
#pragma unroll
            for (int q = 0; q < 4; q++) {
                int cg = c + q;
                int off = r * WDP + (cg >> 3) * 18 + (cg & 7) * 2;
                *(unsigned long long*)&Wd[off] = pack2(vv[q], vv[q]);
            }
        }
        __syncthreads();
#pragma unroll 4
        for (int k = 0; k < 32; k++) {
            unsigned long long a[4], wd[8];
#pragma unroll
            for (int p = 0; p < 4; p++)
                a[p] = *(const unsigned long long*)&Ast[k * AP + tr * 8 + 2 * p];
#pragma unroll
            for (int c = 0; c < 8; c++)
                wd[c] = *(const unsigned long long*)&Wd[k * WDP + tc * 18 + 2 * c];
#pragma unroll
            for (int p = 0; p < 4; p++)
#pragma unroll
                for (int c = 0; c < 8; c++) fma2(acc[p][c], a[p], wd[c]);
        }
        __syncthreads();
    }

    bool isZ = (tc >= 8);
    int col = (tc & 7) * 8;
    float bv[8];
#pragma unroll
    for (int c = 0; c < 8; c++) bv[c] = isZ ? bias[col + c] : 0.f;
    float* O = isZ ? Z : Y;
#pragma unroll
    for (int p = 0; p < 4; p++) {
        float lo[8], hi[8];
#pragma unroll
        for (int c = 0; c < 8; c++) unpack2(acc[p][c], lo[c], hi[c]);
        int r0 = m0 + tr * 8 + 2 * p;
        if (r0 < NN) {
            float4 v0 = make_float4(lo[0] + bv[0], lo[1] + bv[1], lo[2] + bv[2], lo[3] + bv[3]);
            float4 v1 = make_float4(lo[4] + bv[4], lo[5] + bv[5], lo[6] + bv[6], lo[7] + bv[7]);
            *(float4*)&O[r0 * 64 + col] = v0;
            *(float4*)&O[r0 * 64 + col + 4] = v1;
        }
        if (r0 + 1 < NN) {
            float4 v0 = make_float4(hi[0] + bv[0], hi[1] + bv[1], hi[2] + bv[2], hi[3] + bv[3]);
            float4 v1 = make_float4(hi[4] + bv[4], hi[5] + bv[5], hi[6] + bv[6], hi[7] + bv[7]);
            *(float4*)&O[(r0 + 1) * 64 + col] = v0;
            *(float4*)&O[(r0 + 1) * 64 + col + 4] = v1;
        }
    }
}

// -------- aggregation + combine: h = ic * sum(Y[src]) + Z  (warp/node) ------
// Uniform 4-batched index loads (L1-hit, line shared by all lanes) feed
// 4 independent gathers -> MLP 4, no SHFL traffic.
template <bool POOL>
__global__ void aggregate_kernel(float* __restrict__ Hout) {
    int w = (blockIdx.x * blockDim.x + threadIdx.x) >> 5;
    int lane = threadIdx.x & 31;
    if (w >= NN) return;
    int s0 = g_rowstart[w], s1 = g_rowstart[w + 1];
    float ax = 0.f, ay = 0.f;
    int k = s0;
    for (; k + 4 <= s1; k += 4) {
        int i0 = g_csr_src[k], i1 = g_csr_src[k + 1];
        int i2 = g_csr_src[k + 2], i3 = g_csr_src[k + 3];
        float2 v0 = *(const float2*)&g_y[i0 * 64 + lane * 2];
        float2 v1 = *(const float2*)&g_y[i1 * 64 + lane * 2];
        float2 v2 = *(const float2*)&g_y[i2 * 64 + lane * 2];
        float2 v3 = *(const float2*)&g_y[i3 * 64 + lane * 2];
        ax += v0.x + v1.x + v2.x + v3.x;
        ay += v0.y + v1.y + v2.y + v3.y;
    }
    for (; k < s1; k++) {
        int s = g_csr_src[k];
        float2 v = *(const float2*)&g_y[s * 64 + lane * 2];
        ax += v.x; ay += v.y;
    }
    float ic = g_invcnt[w];
    float2 z = *(const float2*)&g_z[w * 64 + lane * 2];
    float ox = ax * ic + z.x, oy = ay * ic + z.y;
    if (POOL) {
        int g = g_batch[w];
        atomicAdd(&g_pacc[g * 64 + lane * 2 + 0], ox);
        atomicAdd(&g_pacc[g * 64 + lane * 2 + 1], oy);
        if (lane == 0) atomicAdd(&g_pcnt[g], 1.f);
    } else {
        float2 o; o.x = ox; o.y = oy;
        *(float2*)&Hout[w * 64 + lane * 2] = o;
    }
}

// ---------------- fused head layer: X = tanh(BN(A@W + b)) -------------------
// DIV=true: stage A = pacc * (1/pcnt) (global mean pool normalization fused).
template <int K, int N, bool DIV>
__launch_bounds__(256)
__global__ void head_kernel(const float* __restrict__ A, const float* __restrict__ W,
                            const float* __restrict__ b,
                            const float* __restrict__ gam, const float* __restrict__ bet,
                            float* __restrict__ X) {
    __shared__ float As[256 * 33];
    __shared__ float inv[256];
    int j = blockIdx.x, i = threadIdx.x;
    if (DIV) {
        inv[i] = 1.0f / fmaxf(g_pcnt[i], 1.0f);
        __syncthreads();
    }
    float acc = b[j];
    for (int k0 = 0; k0 < K; k0 += 32) {
#pragma unroll
        for (int t = 0; t < 32; t++) {
            int idx = t * 256 + i;
            int r = idx >> 5, c = idx & 31;
            float v = A[r * K + k0 + c];
            if (DIV) v *= inv[r];
            As[r * 33 + c] = v;
        }
        __syncthreads();
#pragma unroll
        for (int kk = 0; kk < 32; kk++)
            acc = fmaf(As[i * 33 + kk], W[(k0 + kk) * N + j], acc);
        __syncthreads();
    }
    __shared__ float red[256];
    red[i] = acc;
    __syncthreads();
    for (int off = 128; off > 0; off >>= 1) {
        if (i < off) red[i] += red[i + off];
        __syncthreads();
    }
    float mean = red[0] * (1.f / 256.f);
    __syncthreads();
    float d = acc - mean;
    red[i] = d * d;
    __syncthreads();
    for (int off = 128; off > 0; off >>= 1) {
        if (i < off) red[i] += red[i + off];
        __syncthreads();
    }
    float var = red[0] * (1.f / 256.f);
    X[i * N + j] = tanhf(d * rsqrtf(var + BN_EPS) * gam[j] + bet[j]);
}

// final linear (no BN); also re-zeroes g_pacc / g_pcnt for the next replay
__launch_bounds__(256)
__global__ void final_kernel(const float* __restrict__ A, const float* __restrict__ W,
                             const float* __restrict__ b, float* __restrict__ out) {
    __shared__ float As[256 * 33];
    int j = blockIdx.x, i = threadIdx.x;   // 10 blocks x 256 rows
    float acc = b[j];
    for (int k0 = 0; k0 < 64; k0 += 32) {
#pragma unroll
        for (int t = 0; t < 32; t++) {
            int idx = t * 256 + i;
            int r = idx >> 5, c = idx & 31;
            As[r * 33 + c] = A[r * 64 + k0 + c];
        }
        __syncthreads();
#pragma unroll
        for (int kk = 0; kk < 32; kk++)
            acc = fmaf(As[i * 33 + kk], W[(k0 + kk) * 10 + j], acc);
        __syncthreads();
    }
    out[i * 10 + j] = acc;
    // replay-state reset (runs after heads consumed pacc/pcnt)
    int tid = j * 256 + i;                 // 2560 linear threads
    for (int t = tid; t < NG * H; t += 2560) g_pacc[t] = 0.f;
    if (tid < NG) g_pcnt[tid] = 0.f;
}

// ------------------------ launch --------------------------------------------
extern "C" void kernel_launch(void* const* d_in, const int* in_sizes, int n_in,
                              void* d_out, int out_size) {
    const float* x      = (const float*)d_in[0];
    const void*  ei     = d_in[1];
    const void*  bt     = d_in[2];
    const float* W1l    = (const float*)d_in[3];
    const float* b1l    = (const float*)d_in[4];
    const float* W1r    = (const float*)d_in[5];
    const float* W2l    = (const float*)d_in[6];
    const float* b2l    = (const float*)d_in[7];
    const float* W2r    = (const float*)d_in[8];
    const float* W3l    = (const float*)d_in[9];
    const float* b3l    = (const float*)d_in[10];
    const float* W3r    = (const float*)d_in[11];
    const float* lin1_w = (const float*)d_in[12];
    const float* lin1_b = (const float*)d_in[13];
    const float* g1     = (const float*)d_in[14];
    const float* be1    = (const float*)d_in[15];
    const float* lin2_w = (const float*)d_in[16];
    const float* lin2_b = (const float*)d_in[17];
    const float* g2     = (const float*)d_in[18];
    const float* be2    = (const float*)d_in[19];
    const float* lin3_w = (const float*)d_in[20];
    const float* lin3_b = (const float*)d_in[21];
    const float* g3     = (const float*)d_in[22];
    const float* be3    = (const float*)d_in[23];
    const float* lin4_w = (const float*)d_in[24];
    const float* lin4_b = (const float*)d_in[25];
    float* out = (float*)d_out;

    float *pY, *pZ, *pHA, *pHB, *pPacc, *pT1, *pT2, *pT3;
    cudaGetSymbolAddress((void**)&pY,    g_y);
    cudaGetSymbolAddress((void**)&pZ,    g_z);
    cudaGetSymbolAddress((void**)&pHA,   g_hA);
    cudaGetSymbolAddress((void**)&pHB,   g_hB);
    cudaGetSymbolAddress((void**)&pPacc, g_pacc);
    cudaGetSymbolAddress((void**)&pT1,   g_t1);
    cudaGetSymbolAddress((void**)&pT2,   g_t2);
    cudaGetSymbolAddress((void**)&pT3,   g_t3);

    const int GSM = (32 * AP + 32 * WDP) * 4;   // (4160 + 9216) * 4 = 53504 B
    cudaFuncSetAttribute(gemm_fused<128>, cudaFuncAttributeMaxDynamicSharedMemorySize, GSM);
    cudaFuncSetAttribute(gemm_fused<64>,  cudaFuncAttributeMaxDynamicSharedMemorySize, GSM);

    const int EB = (NE + 255) / 256;          // 3125
    const int MB = (NN + 127) / 128;          // 391
    const int WB = (NN * 32 + 255) / 256;     // 6250

    convert_kernel<<<EB, 256>>>(ei, bt);                                      // 0
    scan_kernel<<<1, 1024>>>();                                               // 1
    fill_kernel<<<EB, 256>>>();                                               // 2
    gemm_fused<128><<<MB, 256, GSM>>>(x, W1l, W1r, b1l, pY, pZ);              // 3 (profiled)
    aggregate_kernel<false><<<WB, 256>>>(pHA);

    // ---- layer 2 (K=64) ----
    gemm_fused<64><<<MB, 256, GSM>>>(pHA, W2l, W2r, b2l, pY, pZ);
    aggregate_kernel<false><<<WB, 256>>>(pHB);

    // ---- layer 3 (K=64) + pooling fused ----
    gemm_fused<64><<<MB, 256, GSM>>>(pHB, W3l, W3r, b3l, pY, pZ);
    aggregate_kernel<true><<<WB, 256>>>(nullptr);

    // ---- MLP head (pool-normalize fused into head1) ----
    head_kernel<64, 256, true><<<256, 256>>>(pPacc, lin1_w, lin1_b, g1, be1, pT1);
    head_kernel<256, 128, false><<<128, 256>>>(pT1, lin2_w, lin2_b, g2, be2, pT2);
    head_kernel<128, 64, false><<<64, 256>>>(pT2, lin3_w, lin3_b, g3, be3, pT3);
    final_kernel<<<10, 256>>>(pT3, lin4_w, lin4_b, out);
}